// round 13
// baseline (speedup 1.0000x reference)
#include <cuda_runtime.h>
#include <cstdint>

#define BS 4
#define SL 128
#define DM 512
#define NH 8
#define DP 64

#define NBLK 592   // 4 blocks/SM x 148 SMs, guaranteed co-resident

typedef unsigned long long u64;

// ---------------- scratch (device globals; no allocation allowed) ----------------
__device__ int   g_idx[3][SL][SL];        // 0:q 1:k 2:v permutations
__device__ float g_qp[BS*SL*DM];
__device__ float g_kp[BS*SL*DM];
__device__ float g_vp[BS*SL*DM];
__device__ float g_P [BS*NH*SL*SL];       // exp(G - rowmax)
__device__ float g_R [BS*NH*SL*SL];       // 1 / prefix-sum
__device__ float g_eff[BS*SL*DM];
__device__ u64   g_bar = 0;               // monotone grid-barrier counter (never reset)

// ---------------- packed fp32x2 helpers (sm_103a FFMA2) ----------------
__device__ __forceinline__ u64 pk2(float lo, float hi) {
    u64 r; asm("mov.b64 %0, {%1,%2};" : "=l"(r) : "f"(lo), "f"(hi)); return r;
}
__device__ __forceinline__ void upk2(u64 v, float& lo, float& hi) {
    asm("mov.b64 {%0,%1}, %2;" : "=f"(lo), "=f"(hi) : "l"(v));
}
__device__ __forceinline__ u64 ffma2(u64 a, u64 b, u64 c) {
    u64 d; asm("fma.rn.f32x2 %0, %1, %2, %3;" : "=l"(d) : "l"(a), "l"(b), "l"(c)); return d;
}

// ---------------- monotone-epoch grid barrier (graph-replay safe) ----------------
__device__ __forceinline__ void grid_barrier() {
    __syncthreads();
    if (threadIdx.x == 0) {
        __threadfence();
        u64 ticket = atomicAdd(&g_bar, 1ULL);
        u64 target = (ticket / NBLK + 1ULL) * (u64)NBLK;
        while (*(volatile u64*)&g_bar < target) { }
        __threadfence();
    }
    __syncthreads();
}

// ---------------- threefry2x32 (JAX-compatible) ----------------
__device__ __forceinline__ uint2 tf2x32(uint32_t k0, uint32_t k1, uint32_t x0, uint32_t x1) {
    uint32_t k2 = k0 ^ k1 ^ 0x1BD11BDAu;
    x0 += k0; x1 += k1;
#define TFR(R) { x0 += x1; x1 = (x1 << R) | (x1 >> (32 - R)); x1 ^= x0; }
    TFR(13) TFR(15) TFR(26) TFR(6)
    x0 += k1; x1 += k2 + 1u;
    TFR(17) TFR(29) TFR(16) TFR(24)
    x0 += k2; x1 += k0 + 2u;
    TFR(13) TFR(15) TFR(26) TFR(6)
    x0 += k0; x1 += k1 + 3u;
    TFR(17) TFR(29) TFR(16) TFR(24)
    x0 += k1; x1 += k2 + 4u;
    TFR(13) TFR(15) TFR(26) TFR(6)
    x0 += k2; x1 += k0 + 5u;
#undef TFR
    return make_uint2(x0, x1);
}

// ---------------- 32x64 GEMM tile (FFMA2): C[bm:+32, bn:+64] = A@B + bias ------
__device__ __forceinline__ void gemm_tile32(const float* __restrict__ A,
                                            const float* __restrict__ B,
                                            const float* __restrict__ bias,
                                            float* __restrict__ C,
                                            int bm, int bn, float* sbuf) {
    float (*As)[36] = (float(*)[36])sbuf;              // [k][m]
    float (*Bs)[68] = (float(*)[68])(sbuf + 16 * 36);  // [k][n]
    int tid = threadIdx.x;
    int tr = tid >> 4, tc = tid & 15;
    u64 acc2[2][2];
    acc2[0][0] = acc2[0][1] = acc2[1][0] = acc2[1][1] = 0ull;

    int lm = tid >> 2, lkq = (tid & 3) << 2;   // A loader (threads 0..127)
    int lk = tid >> 4, lnq = (tid & 15) << 2;  // B loader
    bool loadA = (tid < 128);

    float4 a = make_float4(0.f, 0.f, 0.f, 0.f);
    if (loadA) a = *(const float4*)&A[(bm + lm) * 512 + lkq];
    float4 bb = *(const float4*)&B[lk * 512 + bn + lnq];

    for (int k0 = 0; k0 < 512; k0 += 16) {
        if (loadA) {
            As[lkq + 0][lm] = a.x; As[lkq + 1][lm] = a.y;
            As[lkq + 2][lm] = a.z; As[lkq + 3][lm] = a.w;
        }
        *(float4*)&Bs[lk][lnq] = bb;
        __syncthreads();
        if (k0 + 16 < 512) {
            if (loadA) a = *(const float4*)&A[(bm + lm) * 512 + k0 + 16 + lkq];
            bb = *(const float4*)&B[(k0 + 16 + lk) * 512 + bn + lnq];
        }
        #pragma unroll
        for (int kk = 0; kk < 16; kk++) {
            float a0 = As[kk][tr << 1], a1 = As[kk][(tr << 1) + 1];
            float4 bv = *(float4*)&Bs[kk][tc << 2];
            u64 b01 = pk2(bv.x, bv.y), b23 = pk2(bv.z, bv.w);
            u64 ad;
            ad = pk2(a0, a0);
            acc2[0][0] = ffma2(ad, b01, acc2[0][0]);
            acc2[0][1] = ffma2(ad, b23, acc2[0][1]);
            ad = pk2(a1, a1);
            acc2[1][0] = ffma2(ad, b01, acc2[1][0]);
            acc2[1][1] = ffma2(ad, b23, acc2[1][1]);
        }
        __syncthreads();
    }
    float4 bsv = *(const float4*)&bias[bn + (tc << 2)];
    #pragma unroll
    for (int i = 0; i < 2; i++) {
        float4 o;
        upk2(acc2[i][0], o.x, o.y);
        upk2(acc2[i][1], o.z, o.w);
        o.x += bsv.x; o.y += bsv.y; o.z += bsv.z; o.w += bsv.w;
        *(float4*)&C[(bm + (tr << 1) + i) * 512 + bn + (tc << 2)] = o;
    }
}

// ================= MEGA KERNEL: 4 phases, 3 grid barriers =================
// grid NBLK=592, block 256, smem 37120B, regs capped at 64 (4 blocks/SM).
__global__ void __launch_bounds__(256, 4) mega_kernel(
        const float* __restrict__ q, const float* __restrict__ k,
        const float* __restrict__ v,
        const float* __restrict__ wq, const float* __restrict__ wk,
        const float* __restrict__ wv,
        const float* __restrict__ bq, const float* __restrict__ bk,
        const float* __restrict__ bv,
        const float* __restrict__ wd, const float* __restrict__ bd,
        float* __restrict__ out, float* __restrict__ attn) {
    __shared__ float sbuf[64 * 129 + 8 * 128];   // 9280 floats = 37120B
    int bid = blockIdx.x;
    int tid = threadIdx.x;

    // ======== phase 1: projections (32x64 tiles, 384 units) + perms (64) ========
    if (bid < 384) {
        int z = bid >> 7, tile = bid & 127;          // 128 tiles per matrix
        int bm = (tile >> 3) << 5, bn = (tile & 7) << 6;
        const float *A, *B, *bias; float* C;
        if (z == 0)      { A = q; B = wq; bias = bq; C = g_qp; }
        else if (z == 1) { A = k; B = wk; bias = bk; C = g_kp; }
        else             { A = v; B = wv; bias = bv; C = g_vp; }
        gemm_tile32(A, B, bias, C, bm, bn, sbuf);
    } else if (bid < 448) {
        float* keys = sbuf;                          // keys[2][SL]
        int id = bid - 384;
        int half = tid >> 7, j = tid & 127;
        int t = id * 2 + half;
        for (int p = 0; p < 3; p++) {
            uint2 fk = tf2x32(0u, 42u, 0u, (uint32_t)p);
            float key;
            if (j < t) {
                uint32_t i = (uint32_t)(t * SL + j);
                uint2 r = tf2x32(fk.x, fk.y, 0u, i);
                uint32_t bits = r.x ^ r.y;
                key = __uint_as_float((bits >> 9) | 0x3f800000u) - 1.0f;
            } else {
                key = (float)j + 2.0f;
            }
            keys[half * SL + j] = key;
            __syncthreads();
            int rank = 0;
            #pragma unroll 8
            for (int jj = 0; jj < SL; jj++) {
                float o = keys[half * SL + jj];
                rank += (o < key) || (o == key && jj < j);
            }
            g_idx[p][t][rank] = j;
            __syncthreads();
        }
    }

    grid_barrier();

    // ======== phase 2: gp (512 units: 8 G-rows x 128 cols each) ========
    if (bid < 512) {
        float (*ksT)[129] = (float(*)[129])sbuf;
        float (*Gs)[128]  = (float(*)[128])(sbuf + 64 * 129);
        int unit = bid;
        int rc = unit & 15, h = (unit >> 4) & 7, b = unit >> 7;
        int i0 = rc << 3;
        int j = tid & 127;
        int ihalf = tid >> 7;

        #pragma unroll
        for (int u = 0; u < 8; u++) {
            int lin = tid + u * 256;
            int j2 = lin >> 4;
            int dq = (lin & 15) << 2;
            float4 kv = *(const float4*)&g_kp[((b * SL + j2) << 9) + (h << 6) + dq];
            ksT[dq + 0][j2] = kv.x;
            ksT[dq + 1][j2] = kv.y;
            ksT[dq + 2][j2] = kv.z;
            ksT[dq + 3][j2] = kv.w;
        }
        __syncthreads();

        float acc[4];
        #pragma unroll
        for (int r = 0; r < 4; r++) acc[r] = 0.f;
        const float* qbase = g_qp + ((b * SL + i0) << 9) + (h << 6);
        #pragma unroll
        for (int d4 = 0; d4 < 16; d4++) {
            float k0v = ksT[(d4 << 2) + 0][j];
            float k1v = ksT[(d4 << 2) + 1][j];
            float k2v = ksT[(d4 << 2) + 2][j];
            float k3v = ksT[(d4 << 2) + 3][j];
            #pragma unroll
            for (int r = 0; r < 4; r++) {
                float4 qv = __ldg((const float4*)&qbase[(((ihalf << 2) + r) << 9) + (d4 << 2)]);
                acc[r] += qv.x * k0v + qv.y * k1v + qv.z * k2v + qv.w * k3v;
            }
        }
        #pragma unroll
        for (int r = 0; r < 4; r++) Gs[(ihalf << 2) + r][j] = acc[r] * 0.125f;
        __syncthreads();

        int w = tid >> 5, lane = tid & 31;
        {
            int i = w;
            float4 g = *(float4*)&Gs[i][lane << 2];
            float m = fmaxf(fmaxf(g.x, g.y), fmaxf(g.z, g.w));
            #pragma unroll
            for (int off = 16; off; off >>= 1) m = fmaxf(m, __shfl_xor_sync(0xffffffffu, m, off));
            float e0 = __expf(g.x - m), e1 = __expf(g.y - m);
            float e2 = __expf(g.z - m), e3 = __expf(g.w - m);
            int rowbase = ((b * NH + h) * SL + i0 + i) * SL;
            *(float4*)&g_P[rowbase + (lane << 2)] = make_float4(e0, e1, e2, e3);
            float s1 = e0 + e1, s2 = s1 + e2, s3 = s2 + e3;
            float tot = s3, sc = tot;
            #pragma unroll
            for (int off = 1; off < 32; off <<= 1) {
                float o = __shfl_up_sync(0xffffffffu, sc, off);
                if (lane >= off) sc += o;
            }
            float excl = sc - tot;
            *(float4*)&g_R[rowbase + (lane << 2)] =
                make_float4(1.0f / (excl + e0), 1.0f / (excl + s1),
                            1.0f / (excl + s2), 1.0f / (excl + s3));
        }
    }

    grid_barrier();

    // ======== phase 3: attn (units 0..4095) + eff (units 4096..4607) ========
    for (int unit = bid; unit < 4608; unit += NBLK) {
        if (unit < 4096) {
            // ---- attn unit: (b,h,t) ----
            int t = unit & 127, h = (unit >> 7) & 7, b = unit >> 10;
            int* idxk_s = (int*)sbuf;                 // 128
            int* idxq_s = (int*)sbuf + 128;           // 128
            float* pbufb = sbuf + 256;                // [8][2][128]
            if (tid < SL) {
                idxk_s[tid] = g_idx[1][t][tid];
                idxq_s[tid] = g_idx[0][t][tid];
            }
            __syncthreads();
            float uval = 1.0f / (float)(t + 1);
            float* base = attn + (((size_t)((b * SL + t) * NH + h)) << 14);
            const float* Pbh = g_P + ((size_t)(b * NH + h) << 14);
            const float* Rbh = g_R + ((size_t)(b * NH + h) << 14);
            int lane = tid & 31, w = tid >> 5;
            int k0 = lane << 2;
            int  j0 = idxk_s[k0], j1 = idxk_s[k0 + 1], j2 = idxk_s[k0 + 2], j3 = idxk_s[k0 + 3];
            bool p0 = (k0 <= t), p1 = (k0 + 1 <= t), p2 = (k0 + 2 <= t), p3 = (k0 + 3 <= t);

            for (int qq = w; qq <= t; qq += 16) {
                int q2 = qq + 8;
                bool have2 = (q2 <= t);
                int iq0 = idxq_s[qq];
                float r0 = __ldg(&Rbh[iq0 * SL + t]);
                float4 P0 = __ldg((const float4*)&Pbh[iq0 * SL + k0]);
                float r1 = 0.f; float4 P1;
                if (have2) {
                    int iq1 = idxq_s[q2];
                    r1 = __ldg(&Rbh[iq1 * SL + t]);
                    P1 = __ldg((const float4*)&Pbh[iq1 * SL + k0]);
                }
                *(float4*)&pbufb[(w * 2 + 0) * SL + k0] = P0;
                if (have2) *(float4*)&pbufb[(w * 2 + 1) * SL + k0] = P1;
                __syncwarp();
                const float* pa = pbufb + (w * 2 + 0) * SL;
                float4 v0;
                v0.x = p0 ? pa[j0] * r0 : 0.f;
                v0.y = p1 ? pa[j1] * r0 : 0.f;
                v0.z = p2 ? pa[j2] * r0 : 0.f;
                v0.w = p3 ? pa[j3] * r0 : 0.f;
                __stcs((float4*)&base[qq * SL + k0], v0);
                if (have2) {
                    const float* pb = pbufb + (w * 2 + 1) * SL;
                    float4 v1;
                    v1.x = p0 ? pb[j0] * r1 : 0.f;
                    v1.y = p1 ? pb[j1] * r1 : 0.f;
                    v1.z = p2 ? pb[j2] * r1 : 0.f;
                    v1.w = p3 ? pb[j3] * r1 : 0.f;
                    __stcs((float4*)&base[q2 * SL + k0], v1);
                }
                __syncwarp();
            }
            float4 uv;
            uv.x = p0 ? uval : 0.f;
            uv.y = p1 ? uval : 0.f;
            uv.z = p2 ? uval : 0.f;
            uv.w = p3 ? uval : 0.f;
            int u0 = (w > t) ? w : (w + ((t - w) / 8 + 1) * 8);
            for (int q2 = u0; q2 < SL; q2 += 8) {
                __stcs((float4*)&base[q2 * SL + k0], uv);
            }
            __syncthreads();
        } else {
            // ---- eff unit: (b,t), permutation-inverted sequential V reads ----
            int u2 = unit - 4096;
            int t = u2 & 127, b = u2 >> 7;
            int* inv_s = (int*)sbuf;                  // 128
            float* ws = sbuf + 128;                   // [8][128]
            if (tid < SL) inv_s[g_idx[2][t][tid]] = tid;
            __syncthreads();
            for (int idx = tid; idx < NH * SL; idx += 256) {
                int h = idx >> 7, j = idx & 127;
                int kk = inv_s[j];
                float val = 0.f;
                if (kk <= t) {
                    int jj = g_idx[1][t][kk];
                    int rb = ((b * NH + h) * SL + t) * SL;
                    val = g_P[rb + jj] * g_R[rb + t];
                }
                ws[h * SL + j] = val;
            }
            __syncthreads();
            int h0 = tid >> 6;
            int c1 = tid + 256, h1 = c1 >> 6;
            const float* Vb = g_vp + ((size_t)(b * SL) << 9);
            float a0 = 0.f, a1 = 0.f, b0 = 0.f, b1 = 0.f;
            float c0a = 0.f, c1a = 0.f, d0a = 0.f, d1a = 0.f;
            int j = 0;
            for (; j + 3 <= t; j += 4) {
                const float* r0 = Vb + ((size_t)(j    ) << 9);
                const float* r1 = Vb + ((size_t)(j + 1) << 9);
                const float* r2 = Vb + ((size_t)(j + 2) << 9);
                const float* r3 = Vb + ((size_t)(j + 3) << 9);
                a0  += ws[h0 * SL + j    ] * __ldg(&r0[tid]);
                a1  += ws[h1 * SL + j    ] * __ldg(&r0[c1]);
                b0  += ws[h0 * SL + j + 1] * __ldg(&r1[tid]);
                b1  += ws[h1 * SL + j + 1] * __ldg(&r1[c1]);
                c0a += ws[h0 * SL + j + 2] * __ldg(&r2[tid]);
                c1a += ws[h1 * SL + j + 2] * __ldg(&r2[c1]);
                d0a += ws[h0 * SL + j + 3] * __ldg(&r3[tid]);
                d1a += ws[h1 * SL + j + 3] * __ldg(&r3[c1]);
            }
            for (; j <= t; j++) {
                const float* r0 = Vb + ((size_t)j << 9);
                a0 += ws[h0 * SL + j] * __ldg(&r0[tid]);
                a1 += ws[h1 * SL + j] * __ldg(&r0[c1]);
            }
            size_t ob = (size_t)(b * SL + t) << 9;
            g_eff[ob + tid] = (a0 + b0) + (c0a + d0a);
            g_eff[ob + c1]  = (a1 + b1) + (c1a + d1a);
            __syncthreads();
        }
    }

    grid_barrier();

    // ======== phase 4: out = g_eff @ wd + bd (128 32x64 tiles) ========
    if (bid < 128) {
        int bm = (bid >> 3) << 5, bn = (bid & 7) << 6;
        gemm_tile32(g_eff, wd, bd, out, bm, bn, sbuf);
    }
}

// ---------------- launch: ONE kernel node ----------------
extern "C" void kernel_launch(void* const* d_in, const int* in_sizes, int n_in,
                              void* d_out, int out_size) {
    const float* q  = (const float*)d_in[0];
    const float* k  = (const float*)d_in[1];
    const float* v  = (const float*)d_in[2];
    // d_in[3] = mask (recomputed analytically, unused)
    const float* wq = (const float*)d_in[4];
    const float* bq = (const float*)d_in[5];
    const float* wk = (const float*)d_in[6];
    const float* bk = (const float*)d_in[7];
    const float* wv = (const float*)d_in[8];
    const float* bv = (const float*)d_in[9];
    const float* wd = (const float*)d_in[10];
    const float* bd = (const float*)d_in[11];

    float* out  = (float*)d_out;                 // (BS,SL,DM)
    float* attn = out + (size_t)BS * SL * DM;    // (BS,SL,NH,SL,SL)

    mega_kernel<<<NBLK, 256>>>(q, k, v, wq, wk, wv, bq, bk, bv, wd, bd, out, attn);
}

// round 14
// speedup vs baseline: 1.0213x; 1.0213x over previous
#include <cuda_runtime.h>
#include <cstdint>

#define BS 4
#define SL 128
#define DM 512
#define NH 8
#define DP 64

typedef unsigned long long u64;

// ---------------- scratch (device globals; no allocation allowed) ----------------
__device__ int   g_idx[3][SL][SL];        // 0:q 1:k 2:v permutations
__device__ float g_qp[BS*SL*DM];
__device__ float g_kp[BS*SL*DM];
__device__ float g_vp[BS*SL*DM];
__device__ float g_P [BS*NH*SL*SL];       // exp(G - rowmax)
__device__ float g_R [BS*NH*SL*SL];       // 1 / prefix-sum
__device__ float g_eff[BS*SL*DM];

// ---- side stream + events (host objects, created at static-init) ----
struct SideStream {
    cudaStream_t s1;
    cudaEvent_t eg, ed;
    SideStream() {
        cudaStreamCreateWithFlags(&s1, cudaStreamNonBlocking);
        cudaEventCreateWithFlags(&eg, cudaEventDisableTiming);
        cudaEventCreateWithFlags(&ed, cudaEventDisableTiming);
    }
};
static SideStream g_ss;

// ---------------- packed fp32x2 helpers (sm_103a FFMA2) ----------------
__device__ __forceinline__ u64 pk2(float lo, float hi) {
    u64 r; asm("mov.b64 %0, {%1,%2};" : "=l"(r) : "f"(lo), "f"(hi)); return r;
}
__device__ __forceinline__ void upk2(u64 v, float& lo, float& hi) {
    asm("mov.b64 {%0,%1}, %2;" : "=f"(lo), "=f"(hi) : "l"(v));
}
__device__ __forceinline__ u64 ffma2(u64 a, u64 b, u64 c) {
    u64 d; asm("fma.rn.f32x2 %0, %1, %2, %3;" : "=l"(d) : "l"(a), "l"(b), "l"(c)); return d;
}

// ---------------- threefry2x32 (JAX-compatible) ----------------
__device__ __forceinline__ uint2 tf2x32(uint32_t k0, uint32_t k1, uint32_t x0, uint32_t x1) {
    uint32_t k2 = k0 ^ k1 ^ 0x1BD11BDAu;
    x0 += k0; x1 += k1;
#define TFR(R) { x0 += x1; x1 = (x1 << R) | (x1 >> (32 - R)); x1 ^= x0; }
    TFR(13) TFR(15) TFR(26) TFR(6)
    x0 += k1; x1 += k2 + 1u;
    TFR(17) TFR(29) TFR(16) TFR(24)
    x0 += k2; x1 += k0 + 2u;
    TFR(13) TFR(15) TFR(26) TFR(6)
    x0 += k0; x1 += k1 + 3u;
    TFR(17) TFR(29) TFR(16) TFR(24)
    x0 += k1; x1 += k2 + 4u;
    TFR(13) TFR(15) TFR(26) TFR(6)
    x0 += k2; x1 += k0 + 5u;
#undef TFR
    return make_uint2(x0, x1);
}

// ---------------- 32x64 GEMM tile (FFMA2): C[bm:+32, bn:+64] = A@B + bias ------
__device__ __forceinline__ void gemm_tile32(const float* __restrict__ A,
                                            const float* __restrict__ B,
                                            const float* __restrict__ bias,
                                            float* __restrict__ C,
                                            int bm, int bn, float* sbuf) {
    float (*As)[36] = (float(*)[36])sbuf;              // [k][m]
    float (*Bs)[68] = (float(*)[68])(sbuf + 16 * 36);  // [k][n]
    int tid = threadIdx.x;
    int tr = tid >> 4, tc = tid & 15;
    u64 acc2[2][2];
    acc2[0][0] = acc2[0][1] = acc2[1][0] = acc2[1][1] = 0ull;

    int lm = tid >> 2, lkq = (tid & 3) << 2;   // A loader (threads 0..127)
    int lk = tid >> 4, lnq = (tid & 15) << 2;  // B loader
    bool loadA = (tid < 128);

    float4 a = make_float4(0.f, 0.f, 0.f, 0.f);
    if (loadA) a = *(const float4*)&A[(bm + lm) * 512 + lkq];
    float4 bb = *(const float4*)&B[lk * 512 + bn + lnq];

    for (int k0 = 0; k0 < 512; k0 += 16) {
        if (loadA) {
            As[lkq + 0][lm] = a.x; As[lkq + 1][lm] = a.y;
            As[lkq + 2][lm] = a.z; As[lkq + 3][lm] = a.w;
        }
        *(float4*)&Bs[lk][lnq] = bb;
        __syncthreads();
        if (k0 + 16 < 512) {
            if (loadA) a = *(const float4*)&A[(bm + lm) * 512 + k0 + 16 + lkq];
            bb = *(const float4*)&B[(k0 + 16 + lk) * 512 + bn + lnq];
        }
        #pragma unroll
        for (int kk = 0; kk < 16; kk++) {
            float a0 = As[kk][tr << 1], a1 = As[kk][(tr << 1) + 1];
            float4 bv = *(float4*)&Bs[kk][tc << 2];
            u64 b01 = pk2(bv.x, bv.y), b23 = pk2(bv.z, bv.w);
            u64 ad;
            ad = pk2(a0, a0);
            acc2[0][0] = ffma2(ad, b01, acc2[0][0]);
            acc2[0][1] = ffma2(ad, b23, acc2[0][1]);
            ad = pk2(a1, a1);
            acc2[1][0] = ffma2(ad, b01, acc2[1][0]);
            acc2[1][1] = ffma2(ad, b23, acc2[1][1]);
        }
        __syncthreads();
    }
    float4 bsv = *(const float4*)&bias[bn + (tc << 2)];
    #pragma unroll
    for (int i = 0; i < 2; i++) {
        float4 o;
        upk2(acc2[i][0], o.x, o.y);
        upk2(acc2[i][1], o.z, o.w);
        o.x += bsv.x; o.y += bsv.y; o.z += bsv.z; o.w += bsv.w;
        *(float4*)&C[(bm + (tr << 1) + i) * 512 + bn + (tc << 2)] = o;
    }
}

// ---------------- fused: q/k/v projections (z=0..2, 32x64 tiles) + perms (z=3) --
// grid (8,16,4), block 256
__global__ void __launch_bounds__(256) fused_proj_perm_kernel(
        const float* __restrict__ q, const float* __restrict__ k,
        const float* __restrict__ v,
        const float* __restrict__ wq, const float* __restrict__ wk,
        const float* __restrict__ wv,
        const float* __restrict__ bq, const float* __restrict__ bk,
        const float* __restrict__ bv) {
    __shared__ float sbuf[16 * 36 + 16 * 68];   // 1664 floats
    int z = blockIdx.z;
    int tid = threadIdx.x;
    if (z < 3) {
        int bm = blockIdx.y << 5, bn = blockIdx.x << 6;
        const float *A, *B, *bias; float* C;
        if (z == 0)      { A = q; B = wq; bias = bq; C = g_qp; }
        else if (z == 1) { A = k; B = wk; bias = bk; C = g_kp; }
        else             { A = v; B = wv; bias = bv; C = g_vp; }
        gemm_tile32(A, B, bias, C, bm, bn, sbuf);
        return;
    }
    // perm branch: 128 blocks, one t-row each, 3 perms; threads 0..127 active
    int t = blockIdx.y * 8 + blockIdx.x;     // 0..127
    float* keys = sbuf;
    int j = tid;
    for (int p = 0; p < 3; p++) {
        float key = 0.f;
        if (j < SL) {
            uint2 fk = tf2x32(0u, 42u, 0u, (uint32_t)p);
            if (j < t) {
                uint32_t i = (uint32_t)(t * SL + j);
                uint2 r = tf2x32(fk.x, fk.y, 0u, i);
                uint32_t bits = r.x ^ r.y;
                key = __uint_as_float((bits >> 9) | 0x3f800000u) - 1.0f;
            } else {
                key = (float)j + 2.0f;
            }
            keys[j] = key;
        }
        __syncthreads();
        if (j < SL) {
            int rank = 0;
            #pragma unroll 8
            for (int jj = 0; jj < SL; jj++) {
                float o = keys[jj];
                rank += (o < key) || (o == key && jj < j);
            }
            g_idx[p][t][rank] = j;
        }
        __syncthreads();
    }
}

// ---------------- final dense, WIDE: 32x64 tiles, grid (8,16) = 128 blocks ------
__global__ void __launch_bounds__(256) gemm_out_kernel(
        const float* __restrict__ wd, const float* __restrict__ bd,
        float* __restrict__ out) {
    __shared__ float sbuf[16 * 36 + 16 * 68];
    int bm = blockIdx.y << 5, bn = blockIdx.x << 6;
    gemm_tile32(g_eff, wd, bd, out, bm, bn, sbuf);
}

// ---------------- G = Q K^T /8 per (b,h); P = exp(G-max); R = 1/prefix-sum ------
// grid (16, NH, BS) = 512 blocks, block 256; 8 G-rows x 128 cols per block.
__global__ void gp_kernel() {
    __shared__ float ksT[64][129];    // [d][j]  (stride 129: conflict-free)
    __shared__ float Gs[8][128];
    int rc = blockIdx.x, h = blockIdx.y, b = blockIdx.z;
    int i0 = rc << 3;
    int tid = threadIdx.x;
    int j = tid & 127;
    int ihalf = tid >> 7;

    #pragma unroll
    for (int u = 0; u < 8; u++) {
        int lin = tid + u * 256;
        int j2 = lin >> 4;
        int dq = (lin & 15) << 2;
        float4 kv = *(const float4*)&g_kp[((b * SL + j2) << 9) + (h << 6) + dq];
        ksT[dq + 0][j2] = kv.x;
        ksT[dq + 1][j2] = kv.y;
        ksT[dq + 2][j2] = kv.z;
        ksT[dq + 3][j2] = kv.w;
    }
    __syncthreads();

    float acc[4];
    #pragma unroll
    for (int r = 0; r < 4; r++) acc[r] = 0.f;
    const float* qbase = g_qp + ((b * SL + i0) << 9) + (h << 6);
    #pragma unroll
    for (int d4 = 0; d4 < 16; d4++) {
        float k0v = ksT[(d4 << 2) + 0][j];
        float k1v = ksT[(d4 << 2) + 1][j];
        float k2v = ksT[(d4 << 2) + 2][j];
        float k3v = ksT[(d4 << 2) + 3][j];
        #pragma unroll
        for (int r = 0; r < 4; r++) {
            float4 qv = __ldg((const float4*)&qbase[(((ihalf << 2) + r) << 9) + (d4 << 2)]);
            acc[r] += qv.x * k0v + qv.y * k1v + qv.z * k2v + qv.w * k3v;
        }
    }
    #pragma unroll
    for (int r = 0; r < 4; r++) Gs[(ihalf << 2) + r][j] = acc[r] * 0.125f;
    __syncthreads();

    int w = tid >> 5, lane = tid & 31;
    {
        int i = w;
        float4 g = *(float4*)&Gs[i][lane << 2];
        float m = fmaxf(fmaxf(g.x, g.y), fmaxf(g.z, g.w));
        #pragma unroll
        for (int off = 16; off; off >>= 1) m = fmaxf(m, __shfl_xor_sync(0xffffffffu, m, off));
        float e0 = __expf(g.x - m), e1 = __expf(g.y - m);
        float e2 = __expf(g.z - m), e3 = __expf(g.w - m);
        int rowbase = ((b * NH + h) * SL + i0 + i) * SL;
        *(float4*)&g_P[rowbase + (lane << 2)] = make_float4(e0, e1, e2, e3);
        float s1 = e0 + e1, s2 = s1 + e2, s3 = s2 + e3;
        float tot = s3, sc = tot;
        #pragma unroll
        for (int off = 1; off < 32; off <<= 1) {
            float o = __shfl_up_sync(0xffffffffu, sc, off);
            if (lane >= off) sc += o;
        }
        float excl = sc - tot;
        *(float4*)&g_R[rowbase + (lane << 2)] =
            make_float4(1.0f / (excl + e0), 1.0f / (excl + s1),
                        1.0f / (excl + s2), 1.0f / (excl + s3));
    }
}

// ---------------- big writer: attn[b,t,h,q,k] (256 MB) ----------------
__global__ void __launch_bounds__(256, 6) attn_write_kernel(float* __restrict__ attn) {
    int t = blockIdx.x, h = blockIdx.y, b = blockIdx.z;
    __shared__ int idxk_s[SL];
    __shared__ int idxq_s[SL];
    __shared__ float pbuf[8][2][SL];
    int tid = threadIdx.x;
    if (tid < SL) {
        idxk_s[tid] = g_idx[1][t][tid];
        idxq_s[tid] = g_idx[0][t][tid];
    }
    __syncthreads();
    float uval = 1.0f / (float)(t + 1);
    float* base = attn + (((size_t)((b * SL + t) * NH + h)) << 14);
    const float* Pbh = g_P + ((size_t)(b * NH + h) << 14);
    const float* Rbh = g_R + ((size_t)(b * NH + h) << 14);
    int lane = tid & 31, w = tid >> 5;
    int k0 = lane << 2;
    int  j0 = idxk_s[k0], j1 = idxk_s[k0 + 1], j2 = idxk_s[k0 + 2], j3 = idxk_s[k0 + 3];
    bool p0 = (k0 <= t), p1 = (k0 + 1 <= t), p2 = (k0 + 2 <= t), p3 = (k0 + 3 <= t);

    for (int qq = w; qq <= t; qq += 16) {
        int q2 = qq + 8;
        bool have2 = (q2 <= t);
        int iq0 = idxq_s[qq];
        float r0 = __ldg(&Rbh[iq0 * SL + t]);
        float4 P0 = __ldg((const float4*)&Pbh[iq0 * SL + k0]);
        float r1 = 0.f; float4 P1;
        if (have2) {
            int iq1 = idxq_s[q2];
            r1 = __ldg(&Rbh[iq1 * SL + t]);
            P1 = __ldg((const float4*)&Pbh[iq1 * SL + k0]);
        }
        *(float4*)&pbuf[w][0][k0] = P0;
        if (have2) *(float4*)&pbuf[w][1][k0] = P1;
        __syncwarp();
        const float* pa = pbuf[w][0];
        float4 v0;
        v0.x = p0 ? pa[j0] * r0 : 0.f;
        v0.y = p1 ? pa[j1] * r0 : 0.f;
        v0.z = p2 ? pa[j2] * r0 : 0.f;
        v0.w = p3 ? pa[j3] * r0 : 0.f;
        __stcs((float4*)&base[qq * SL + k0], v0);
        if (have2) {
            const float* pb = pbuf[w][1];
            float4 v1;
            v1.x = p0 ? pb[j0] * r1 : 0.f;
            v1.y = p1 ? pb[j1] * r1 : 0.f;
            v1.z = p2 ? pb[j2] * r1 : 0.f;
            v1.w = p3 ? pb[j3] * r1 : 0.f;
            __stcs((float4*)&base[q2 * SL + k0], v1);
        }
        __syncwarp();
    }
    float4 uv;
    uv.x = p0 ? uval : 0.f;
    uv.y = p1 ? uval : 0.f;
    uv.z = p2 ? uval : 0.f;
    uv.w = p3 ? uval : 0.f;
    int u0 = (w > t) ? w : (w + ((t - w) / 8 + 1) * 8);
    for (int q2 = u0; q2 < SL; q2 += 8) {
        __stcs((float4*)&base[q2 * SL + k0], uv);
    }
}

// ---------------- eff[b,t,:] = diag ctx row, permutation-inverted ----------------
__global__ void eff_kernel() {
    int t = blockIdx.x, b = blockIdx.y;
    int tid = threadIdx.x;
    __shared__ int inv_s[SL];
    __shared__ float ws[NH][SL];
    if (tid < SL) inv_s[g_idx[2][t][tid]] = tid;
    __syncthreads();
    for (int idx = tid; idx < NH * SL; idx += 256) {
        int h = idx >> 7, j = idx & 127;
        int k = inv_s[j];
        float val = 0.f;
        if (k <= t) {
            int jj = g_idx[1][t][k];
            int rb = ((b * NH + h) * SL + t) * SL;
            val = g_P[rb + jj] * g_R[rb + t];
        }
        ws[h][j] = val;
    }
    __syncthreads();
    int h0 = tid >> 6;
    int c1 = tid + 256, h1 = c1 >> 6;
    const float* Vb = g_vp + ((size_t)(b * SL) << 9);
    float a0 = 0.f, a1 = 0.f, b0 = 0.f, b1 = 0.f;
    float c0a = 0.f, c1a = 0.f, d0a = 0.f, d1a = 0.f;
    int j = 0;
    for (; j + 3 <= t; j += 4) {
        const float* r0 = Vb + ((size_t)(j    ) << 9);
        const float* r1 = Vb + ((size_t)(j + 1) << 9);
        const float* r2 = Vb + ((size_t)(j + 2) << 9);
        const float* r3 = Vb + ((size_t)(j + 3) << 9);
        a0  += ws[h0][j    ] * __ldg(&r0[tid]);
        a1  += ws[h1][j    ] * __ldg(&r0[c1]);
        b0  += ws[h0][j + 1] * __ldg(&r1[tid]);
        b1  += ws[h1][j + 1] * __ldg(&r1[c1]);
        c0a += ws[h0][j + 2] * __ldg(&r2[tid]);
        c1a += ws[h1][j + 2] * __ldg(&r2[c1]);
        d0a += ws[h0][j + 3] * __ldg(&r3[tid]);
        d1a += ws[h1][j + 3] * __ldg(&r3[c1]);
    }
    for (; j <= t; j++) {
        const float* r0 = Vb + ((size_t)j << 9);
        a0 += ws[h0][j] * __ldg(&r0[tid]);
        a1 += ws[h1][j] * __ldg(&r0[c1]);
    }
    size_t ob = (size_t)(b * SL + t) << 9;
    g_eff[ob + tid] = (a0 + b0) + (c0a + d0a);
    g_eff[ob + c1]  = (a1 + b1) + (c1a + d1a);
}

// ---------------- launch: 5 kernel nodes ----------------
//   0 : fused_proj_perm -> gp -(eg)-> attn_write -> (wait ed)
//   s1: (wait eg) eff -> gemm_out -(ed)
extern "C" void kernel_launch(void* const* d_in, const int* in_sizes, int n_in,
                              void* d_out, int out_size) {
    const float* q  = (const float*)d_in[0];
    const float* k  = (const float*)d_in[1];
    const float* v  = (const float*)d_in[2];
    // d_in[3] = mask (recomputed analytically, unused)
    const float* wq = (const float*)d_in[4];
    const float* bq = (const float*)d_in[5];
    const float* wk = (const float*)d_in[6];
    const float* bk = (const float*)d_in[7];
    const float* wv = (const float*)d_in[8];
    const float* bv = (const float*)d_in[9];
    const float* wd = (const float*)d_in[10];
    const float* bd = (const float*)d_in[11];

    float* out  = (float*)d_out;                 // (BS,SL,DM)
    float* attn = out + (size_t)BS * SL * DM;    // (BS,SL,NH,SL,SL)

    cudaStream_t s1 = g_ss.s1;

    fused_proj_perm_kernel<<<dim3(8, 16, 4), 256>>>(q, k, v, wq, wk, wv, bq, bk, bv);
    gp_kernel<<<dim3(16, NH, BS), 256>>>();
    cudaEventRecord(g_ss.eg, 0);

    cudaStreamWaitEvent(s1, g_ss.eg, 0);
    eff_kernel<<<dim3(SL, BS), 256, 0, s1>>>();
    gemm_out_kernel<<<dim3(8, 16, 1), 256, 0, s1>>>(wd, bd, out);
    cudaEventRecord(g_ss.ed, s1);

    attn_write_kernel<<<dim3(SL, NH, BS), 256>>>(attn);

    cudaStreamWaitEvent(0, g_ss.ed, 0);
}

// round 15
// speedup vs baseline: 1.1516x; 1.1276x over previous
#include <cuda_runtime.h>
#include <cstdint>

#define BS 4
#define SL 128
#define DM 512
#define NH 8
#define DP 64

typedef unsigned long long u64;

// ---------------- scratch (device globals; no allocation allowed) ----------------
__device__ int   g_idx[3][SL][SL];        // 0:q 1:k 2:v permutations
__device__ float g_qp[BS*SL*DM];
__device__ float g_kp[BS*SL*DM];
__device__ float g_vp[BS*SL*DM];
__device__ float g_P [BS*NH*SL*SL];       // exp(G - rowmax)
__device__ float g_R [BS*NH*SL*SL];       // 1 / prefix-sum
__device__ float g_eff[BS*SL*DM];

// ---- side stream + events (host objects, created at static-init) ----
struct SideStream {
    cudaStream_t s1;
    cudaEvent_t eg, ed;
    SideStream() {
        cudaStreamCreateWithFlags(&s1, cudaStreamNonBlocking);
        cudaEventCreateWithFlags(&eg, cudaEventDisableTiming);
        cudaEventCreateWithFlags(&ed, cudaEventDisableTiming);
    }
};
static SideStream g_ss;

// ---------------- packed fp32x2 helpers (sm_103a FFMA2) ----------------
__device__ __forceinline__ u64 pk2(float lo, float hi) {
    u64 r; asm("mov.b64 %0, {%1,%2};" : "=l"(r) : "f"(lo), "f"(hi)); return r;
}
__device__ __forceinline__ void upk2(u64 v, float& lo, float& hi) {
    asm("mov.b64 {%0,%1}, %2;" : "=f"(lo), "=f"(hi) : "l"(v));
}
__device__ __forceinline__ u64 ffma2(u64 a, u64 b, u64 c) {
    u64 d; asm("fma.rn.f32x2 %0, %1, %2, %3;" : "=l"(d) : "l"(a), "l"(b), "l"(c)); return d;
}

// ---------------- threefry2x32 (JAX-compatible) ----------------
__device__ __forceinline__ uint2 tf2x32(uint32_t k0, uint32_t k1, uint32_t x0, uint32_t x1) {
    uint32_t k2 = k0 ^ k1 ^ 0x1BD11BDAu;
    x0 += k0; x1 += k1;
#define TFR(R) { x0 += x1; x1 = (x1 << R) | (x1 >> (32 - R)); x1 ^= x0; }
    TFR(13) TFR(15) TFR(26) TFR(6)
    x0 += k1; x1 += k2 + 1u;
    TFR(17) TFR(29) TFR(16) TFR(24)
    x0 += k2; x1 += k0 + 2u;
    TFR(13) TFR(15) TFR(26) TFR(6)
    x0 += k0; x1 += k1 + 3u;
    TFR(17) TFR(29) TFR(16) TFR(24)
    x0 += k1; x1 += k2 + 4u;
    TFR(13) TFR(15) TFR(26) TFR(6)
    x0 += k2; x1 += k0 + 5u;
#undef TFR
    return make_uint2(x0, x1);
}

// ------- 512x512x512 GEMM body, DOUBLE-BUFFERED smem (FFMA2): C = A@B + bias ----
// One __syncthreads per k-tile; smem store of tile i+1 overlaps compute of tile i.
__device__ __forceinline__ void gemm512_body_db(const float* __restrict__ A,
                                                const float* __restrict__ B,
                                                const float* __restrict__ bias,
                                                float* __restrict__ C,
                                                float As[2][16][68], float Bs[2][16][68]) {
    int tid = threadIdx.x;
    int bm = blockIdx.y << 6, bn = blockIdx.x << 6;
    int tr = tid >> 4, tc = tid & 15;
    u64 acc2[4][2];
    #pragma unroll
    for (int i = 0; i < 4; i++) { acc2[i][0] = 0ull; acc2[i][1] = 0ull; }

    int lm = tid >> 2, lkq = (tid & 3) << 2;
    int lk = tid >> 4, lnq = (tid & 15) << 2;

    // prologue: tile 0 -> buf 0
    float4 a  = *(const float4*)&A[(bm + lm) * 512 + lkq];
    float4 bb = *(const float4*)&B[lk * 512 + bn + lnq];
    As[0][lkq + 0][lm] = a.x; As[0][lkq + 1][lm] = a.y;
    As[0][lkq + 2][lm] = a.z; As[0][lkq + 3][lm] = a.w;
    *(float4*)&Bs[0][lk][lnq] = bb;
    __syncthreads();

    for (int k0 = 0; k0 < 512; k0 += 16) {
        int p = (k0 >> 4) & 1;
        bool hasNext = (k0 + 16 < 512);
        if (hasNext) {
            a  = *(const float4*)&A[(bm + lm) * 512 + k0 + 16 + lkq];
            bb = *(const float4*)&B[(k0 + 16 + lk) * 512 + bn + lnq];
        }
        #pragma unroll
        for (int kk = 0; kk < 16; kk++) {
            float4 av = *(float4*)&As[p][kk][tr << 2];
            float4 bv = *(float4*)&Bs[p][kk][tc << 2];
            u64 b01 = pk2(bv.x, bv.y), b23 = pk2(bv.z, bv.w);
            u64 ad;
            ad = pk2(av.x, av.x);
            acc2[0][0] = ffma2(ad, b01, acc2[0][0]);
            acc2[0][1] = ffma2(ad, b23, acc2[0][1]);
            ad = pk2(av.y, av.y);
            acc2[1][0] = ffma2(ad, b01, acc2[1][0]);
            acc2[1][1] = ffma2(ad, b23, acc2[1][1]);
            ad = pk2(av.z, av.z);
            acc2[2][0] = ffma2(ad, b01, acc2[2][0]);
            acc2[2][1] = ffma2(ad, b23, acc2[2][1]);
            ad = pk2(av.w, av.w);
            acc2[3][0] = ffma2(ad, b01, acc2[3][0]);
            acc2[3][1] = ffma2(ad, b23, acc2[3][1]);
        }
        if (hasNext) {
            int pn = p ^ 1;
            As[pn][lkq + 0][lm] = a.x; As[pn][lkq + 1][lm] = a.y;
            As[pn][lkq + 2][lm] = a.z; As[pn][lkq + 3][lm] = a.w;
            *(float4*)&Bs[pn][lk][lnq] = bb;
        }
        __syncthreads();
    }
    float4 bsv = *(const float4*)&bias[bn + (tc << 2)];
    #pragma unroll
    for (int i = 0; i < 4; i++) {
        float4 o;
        upk2(acc2[i][0], o.x, o.y);
        upk2(acc2[i][1], o.z, o.w);
        o.x += bsv.x; o.y += bsv.y; o.z += bsv.z; o.w += bsv.w;
        *(float4*)&C[(bm + (tr << 2) + i) * 512 + bn + (tc << 2)] = o;
    }
}

// ---------------- fused: q/k/v projections (z=0..2, 64x64) + perms (z=3) --------
// grid (8,8,4), block 256
__global__ void fused_proj_perm_kernel(
        const float* __restrict__ q, const float* __restrict__ k,
        const float* __restrict__ v,
        const float* __restrict__ wq, const float* __restrict__ wk,
        const float* __restrict__ wv,
        const float* __restrict__ bq, const float* __restrict__ bk,
        const float* __restrict__ bv) {
    __shared__ float As[2][16][68], Bs[2][16][68];
    int z = blockIdx.z;
    if (z < 3) {
        const float *A, *B, *bias; float* C;
        if (z == 0)      { A = q; B = wq; bias = bq; C = g_qp; }
        else if (z == 1) { A = k; B = wk; bias = bk; C = g_kp; }
        else             { A = v; B = wv; bias = bv; C = g_vp; }
        gemm512_body_db(A, B, bias, C, As, Bs);
        return;
    }
    // perm branch: 64 blocks, 2 sort-rows per perm (tid half), 3 perms
    float* keys = &As[0][0][0];                  // keys[2][SL]
    int id = blockIdx.y * 8 + blockIdx.x;        // 0..63
    int tid = threadIdx.x;
    int half = tid >> 7, j = tid & 127;
    int t = id * 2 + half;                       // 0..127
    for (int p = 0; p < 3; p++) {
        uint2 fk = tf2x32(0u, 42u, 0u, (uint32_t)p);
        float key;
        if (j < t) {
            uint32_t i = (uint32_t)(t * SL + j);
            uint2 r = tf2x32(fk.x, fk.y, 0u, i);
            uint32_t bits = r.x ^ r.y;
            key = __uint_as_float((bits >> 9) | 0x3f800000u) - 1.0f;
        } else {
            key = (float)j + 2.0f;
        }
        keys[half * SL + j] = key;
        __syncthreads();
        int rank = 0;
        #pragma unroll 8
        for (int jj = 0; jj < SL; jj++) {
            float o = keys[half * SL + jj];
            rank += (o < key) || (o == key && jj < j);
        }
        g_idx[p][t][rank] = j;
        __syncthreads();
    }
}

// ---------------- final dense, WIDE: 32x64 tiles, grid (8,16) = 128 blocks ------
__global__ void __launch_bounds__(256) gemm_out_kernel(
        const float* __restrict__ wd, const float* __restrict__ bd,
        float* __restrict__ out) {
    __shared__ float As[16][36];
    __shared__ float Bs[16][68];
    const float* A = g_eff;
    int tid = threadIdx.x;
    int bm = blockIdx.y << 5, bn = blockIdx.x << 6;
    int tr = tid >> 4, tc = tid & 15;
    u64 acc2[2][2];
    acc2[0][0] = acc2[0][1] = acc2[1][0] = acc2[1][1] = 0ull;

    int lm = tid >> 2, lkq = (tid & 3) << 2;
    int lk = tid >> 4, lnq = (tid & 15) << 2;
    bool loadA = (tid < 128);

    float4 a = make_float4(0.f, 0.f, 0.f, 0.f);
    if (loadA) a = *(const float4*)&A[(bm + lm) * 512 + lkq];
    float4 bb = *(const float4*)&wd[lk * 512 + bn + lnq];

    for (int k0 = 0; k0 < 512; k0 += 16) {
        if (loadA) {
            As[lkq + 0][lm] = a.x; As[lkq + 1][lm] = a.y;
            As[lkq + 2][lm] = a.z; As[lkq + 3][lm] = a.w;
        }
        *(float4*)&Bs[lk][lnq] = bb;
        __syncthreads();
        if (k0 + 16 < 512) {
            if (loadA) a = *(const float4*)&A[(bm + lm) * 512 + k0 + 16 + lkq];
            bb = *(const float4*)&wd[(k0 + 16 + lk) * 512 + bn + lnq];
        }
        #pragma unroll
        for (int kk = 0; kk < 16; kk++) {
            float a0 = As[kk][tr << 1], a1 = As[kk][(tr << 1) + 1];
            float4 bv = *(float4*)&Bs[kk][tc << 2];
            u64 b01 = pk2(bv.x, bv.y), b23 = pk2(bv.z, bv.w);
            u64 ad;
            ad = pk2(a0, a0);
            acc2[0][0] = ffma2(ad, b01, acc2[0][0]);
            acc2[0][1] = ffma2(ad, b23, acc2[0][1]);
            ad = pk2(a1, a1);
            acc2[1][0] = ffma2(ad, b01, acc2[1][0]);
            acc2[1][1] = ffma2(ad, b23, acc2[1][1]);
        }
        __syncthreads();
    }
    float4 bsv = *(const float4*)&bd[bn + (tc << 2)];
    #pragma unroll
    for (int i = 0; i < 2; i++) {
        float4 o;
        upk2(acc2[i][0], o.x, o.y);
        upk2(acc2[i][1], o.z, o.w);
        o.x += bsv.x; o.y += bsv.y; o.z += bsv.z; o.w += bsv.w;
        *(float4*)&out[(bm + (tr << 1) + i) * 512 + bn + (tc << 2)] = o;
    }
}

// ---------------- G = Q K^T /8 per (b,h); P = exp(G-max); R = 1/prefix-sum ------
// grid (16, NH, BS) = 512 blocks, block 256; 8 G-rows x 128 cols per block.
__global__ void gp_kernel() {
    __shared__ float ksT[64][129];    // [d][j]  (stride 129: conflict-free)
    __shared__ float Gs[8][128];
    int rc = blockIdx.x, h = blockIdx.y, b = blockIdx.z;
    int i0 = rc << 3;
    int tid = threadIdx.x;
    int j = tid & 127;
    int ihalf = tid >> 7;

    #pragma unroll
    for (int u = 0; u < 8; u++) {
        int lin = tid + u * 256;
        int j2 = lin >> 4;
        int dq = (lin & 15) << 2;
        float4 kv = *(const float4*)&g_kp[((b * SL + j2) << 9) + (h << 6) + dq];
        ksT[dq + 0][j2] = kv.x;
        ksT[dq + 1][j2] = kv.y;
        ksT[dq + 2][j2] = kv.z;
        ksT[dq + 3][j2] = kv.w;
    }
    __syncthreads();

    float acc[4];
    #pragma unroll
    for (int r = 0; r < 4; r++) acc[r] = 0.f;
    const float* qbase = g_qp + ((b * SL + i0) << 9) + (h << 6);
    #pragma unroll
    for (int d4 = 0; d4 < 16; d4++) {
        float k0v = ksT[(d4 << 2) + 0][j];
        float k1v = ksT[(d4 << 2) + 1][j];
        float k2v = ksT[(d4 << 2) + 2][j];
        float k3v = ksT[(d4 << 2) + 3][j];
        #pragma unroll
        for (int r = 0; r < 4; r++) {
            float4 qv = __ldg((const float4*)&qbase[(((ihalf << 2) + r) << 9) + (d4 << 2)]);
            acc[r] += qv.x * k0v + qv.y * k1v + qv.z * k2v + qv.w * k3v;
        }
    }
    #pragma unroll
    for (int r = 0; r < 4; r++) Gs[(ihalf << 2) + r][j] = acc[r] * 0.125f;
    __syncthreads();

    int w = tid >> 5, lane = tid & 31;
    {
        int i = w;
        float4 g = *(float4*)&Gs[i][lane << 2];
        float m = fmaxf(fmaxf(g.x, g.y), fmaxf(g.z, g.w));
        #pragma unroll
        for (int off = 16; off; off >>= 1) m = fmaxf(m, __shfl_xor_sync(0xffffffffu, m, off));
        float e0 = __expf(g.x - m), e1 = __expf(g.y - m);
        float e2 = __expf(g.z - m), e3 = __expf(g.w - m);
        int rowbase = ((b * NH + h) * SL + i0 + i) * SL;
        *(float4*)&g_P[rowbase + (lane << 2)] = make_float4(e0, e1, e2, e3);
        float s1 = e0 + e1, s2 = s1 + e2, s3 = s2 + e3;
        float tot = s3, sc = tot;
        #pragma unroll
        for (int off = 1; off < 32; off <<= 1) {
            float o = __shfl_up_sync(0xffffffffu, sc, off);
            if (lane >= off) sc += o;
        }
        float excl = sc - tot;
        *(float4*)&g_R[rowbase + (lane << 2)] =
            make_float4(1.0f / (excl + e0), 1.0f / (excl + s1),
                        1.0f / (excl + s2), 1.0f / (excl + s3));
    }
}

// ---------------- big writer: attn[b,t,h,q,k] (256 MB) ----------------
__global__ void __launch_bounds__(256, 6) attn_write_kernel(float* __restrict__ attn) {
    int t = blockIdx.x, h = blockIdx.y, b = blockIdx.z;
    __shared__ int idxk_s[SL];
    __shared__ int idxq_s[SL];
    __shared__ float pbuf[8][2][SL];
    int tid = threadIdx.x;
    if (tid < SL) {
        idxk_s[tid] = g_idx[1][t][tid];
        idxq_s[tid] = g_idx[0][t][tid];
    }
    __syncthreads();
    float uval = 1.0f / (float)(t + 1);
    float* base = attn + (((size_t)((b * SL + t) * NH + h)) << 14);
    const float* Pbh = g_P + ((size_t)(b * NH + h) << 14);
    const float* Rbh = g_R + ((size_t)(b * NH + h) << 14);
    int lane = tid & 31, w = tid >> 5;
    int k0 = lane << 2;
    int  j0 = idxk_s[k0], j1 = idxk_s[k0 + 1], j2 = idxk_s[k0 + 2], j3 = idxk_s[k0 + 3];
    bool p0 = (k0 <= t), p1 = (k0 + 1 <= t), p2 = (k0 + 2 <= t), p3 = (k0 + 3 <= t);

    for (int qq = w; qq <= t; qq += 16) {
        int q2 = qq + 8;
        bool have2 = (q2 <= t);
        int iq0 = idxq_s[qq];
        float r0 = __ldg(&Rbh[iq0 * SL + t]);
        float4 P0 = __ldg((const float4*)&Pbh[iq0 * SL + k0]);
        float r1 = 0.f; float4 P1;
        if (have2) {
            int iq1 = idxq_s[q2];
            r1 = __ldg(&Rbh[iq1 * SL + t]);
            P1 = __ldg((const float4*)&Pbh[iq1 * SL + k0]);
        }
        *(float4*)&pbuf[w][0][k0] = P0;
        if (have2) *(float4*)&pbuf[w][1][k0] = P1;
        __syncwarp();
        const float* pa = pbuf[w][0];
        float4 v0;
        v0.x = p0 ? pa[j0] * r0 : 0.f;
        v0.y = p1 ? pa[j1] * r0 : 0.f;
        v0.z = p2 ? pa[j2] * r0 : 0.f;
        v0.w = p3 ? pa[j3] * r0 : 0.f;
        __stcs((float4*)&base[qq * SL + k0], v0);
        if (have2) {
            const float* pb = pbuf[w][1];
            float4 v1;
            v1.x = p0 ? pb[j0] * r1 : 0.f;
            v1.y = p1 ? pb[j1] * r1 : 0.f;
            v1.z = p2 ? pb[j2] * r1 : 0.f;
            v1.w = p3 ? pb[j3] * r1 : 0.f;
            __stcs((float4*)&base[q2 * SL + k0], v1);
        }
        __syncwarp();
    }
    float4 uv;
    uv.x = p0 ? uval : 0.f;
    uv.y = p1 ? uval : 0.f;
    uv.z = p2 ? uval : 0.f;
    uv.w = p3 ? uval : 0.f;
    int u0 = (w > t) ? w : (w + ((t - w) / 8 + 1) * 8);
    for (int q2 = u0; q2 < SL; q2 += 8) {
        __stcs((float4*)&base[q2 * SL + k0], uv);
    }
}

// ---------------- eff[b,t,:] = diag ctx row, permutation-inverted ----------------
__global__ void eff_kernel() {
    int t = blockIdx.x, b = blockIdx.y;
    int tid = threadIdx.x;
    __shared__ int inv_s[SL];
    __shared__ float ws[NH][SL];
    if (tid < SL) inv_s[g_idx[2][t][tid]] = tid;
    __syncthreads();
    for (int idx = tid; idx < NH * SL; idx += 256) {
        int h = idx >> 7, j = idx & 127;
        int k = inv_s[j];
        float val = 0.f;
        if (k <= t) {
            int jj = g_idx[1][t][k];
            int rb = ((b * NH + h) * SL + t) * SL;
            val = g_P[rb + jj] * g_R[rb + t];
        }
        ws[h][j] = val;
    }
    __syncthreads();
    int h0 = tid >> 6;
    int c1 = tid + 256, h1 = c1 >> 6;
    const float* Vb = g_vp + ((size_t)(b * SL) << 9);
    float a0 = 0.f, a1 = 0.f, b0 = 0.f, b1 = 0.f;
    float c0a = 0.f, c1a = 0.f, d0a = 0.f, d1a = 0.f;
    int j = 0;
    for (; j + 3 <= t; j += 4) {
        const float* r0 = Vb + ((size_t)(j    ) << 9);
        const float* r1 = Vb + ((size_t)(j + 1) << 9);
        const float* r2 = Vb + ((size_t)(j + 2) << 9);
        const float* r3 = Vb + ((size_t)(j + 3) << 9);
        a0  += ws[h0][j    ] * __ldg(&r0[tid]);
        a1  += ws[h1][j    ] * __ldg(&r0[c1]);
        b0  += ws[h0][j + 1] * __ldg(&r1[tid]);
        b1  += ws[h1][j + 1] * __ldg(&r1[c1]);
        c0a += ws[h0][j + 2] * __ldg(&r2[tid]);
        c1a += ws[h1][j + 2] * __ldg(&r2[c1]);
        d0a += ws[h0][j + 3] * __ldg(&r3[tid]);
        d1a += ws[h1][j + 3] * __ldg(&r3[c1]);
    }
    for (; j <= t; j++) {
        const float* r0 = Vb + ((size_t)j << 9);
        a0 += ws[h0][j] * __ldg(&r0[tid]);
        a1 += ws[h1][j] * __ldg(&r0[c1]);
    }
    size_t ob = (size_t)(b * SL + t) << 9;
    g_eff[ob + tid] = (a0 + b0) + (c0a + d0a);
    g_eff[ob + c1]  = (a1 + b1) + (c1a + d1a);
}

// ---------------- launch: 5 kernel nodes (R10 structure) ----------------
//   0 : fused_proj_perm -> gp -(eg)-> attn_write -> (wait ed)
//   s1: (wait eg) eff -> gemm_out -(ed)
extern "C" void kernel_launch(void* const* d_in, const int* in_sizes, int n_in,
                              void* d_out, int out_size) {
    const float* q  = (const float*)d_in[0];
    const float* k  = (const float*)d_in[1];
    const float* v  = (const float*)d_in[2];
    // d_in[3] = mask (recomputed analytically, unused)
    const float* wq = (const float*)d_in[4];
    const float* bq = (const float*)d_in[5];
    const float* wk = (const float*)d_in[6];
    const float* bk = (const float*)d_in[7];
    const float* wv = (const float*)d_in[8];
    const float* bv = (const float*)d_in[9];
    const float* wd = (const float*)d_in[10];
    const float* bd = (const float*)d_in[11];

    float* out  = (float*)d_out;                 // (BS,SL,DM)
    float* attn = out + (size_t)BS * SL * DM;    // (BS,SL,NH,SL,SL)

    cudaStream_t s1 = g_ss.s1;

    fused_proj_perm_kernel<<<dim3(8, 8, 4), 256>>>(q, k, v, wq, wk, wv, bq, bk, bv);
    gp_kernel<<<dim3(16, NH, BS), 256>>>();
    cudaEventRecord(g_ss.eg, 0);

    cudaStreamWaitEvent(s1, g_ss.eg, 0);
    eff_kernel<<<dim3(SL, BS), 256, 0, s1>>>();
    gemm_out_kernel<<<dim3(8, 16, 1), 256, 0, s1>>>(wd, bd, out);
    cudaEventRecord(g_ss.ed, s1);

    attn_write_kernel<<<dim3(SL, NH, BS), 256>>>(attn);

    cudaStreamWaitEvent(0, g_ss.ed, 0);
}